// round 1
// baseline (speedup 1.0000x reference)
#include <cuda_runtime.h>
#include <math.h>

// ---------------- problem constants ----------------
#define B_    32
#define HH    28
#define WW    28
#define HID   1024
#define NH    16
#define DH    64
#define ROWS  (B_*HH*WW)        // 25088
#define BNG   (B_*NH)           // 512 groups
#define GSZ   (HH*WW*DH)        // 50176 elems per group

// ALPHA = 1 - tanh(pi/2)
#define ALPHA_F 0.0828476643f
// ln(10000)/16  (invf[j] = exp(-j * this))
#define LN1E4_16 0.5756462732485114f

// ---------------- scratch (static device globals; no runtime alloc) ----------------
__device__ float g_Yq[(size_t)ROWS * HID];     // x @ Wq            102.8 MB
__device__ float g_Yk[(size_t)ROWS * HID];     // x @ Wk            102.8 MB
__device__ float g_xsum[B_ * WW * HID];        // sum_h x           3.7 MB
__device__ float g_isum[B_ * WW * HID];        // sum_h img
__device__ float g_vsum[B_ * WW * HID];        // xsum@Wv + a*isum
__device__ float g_O[(size_t)BNG * GSZ];       // attention out     102.8 MB
__device__ float g_Z[(size_t)ROWS * HID];      // normalized/transposed
__device__ float g_stats[2 * BNG];

// ---------------- SGEMM: C[M,N] = A[M,K] @ B[K,N] (+ addScale*Add) ----------------
// All dims must be multiples of (128,128,8); true for every call here.
__global__ void __launch_bounds__(256, 2) sgemm_kernel(
    const float* __restrict__ A, const float* __restrict__ B, float* __restrict__ C,
    const float* __restrict__ Add, float addScale,
    int M, int N, int K, int lda, int ldb, int ldc)
{
    __shared__ float As[8][128];
    __shared__ float Bs[8][128];

    const int tid   = threadIdx.x;
    const int mBase = blockIdx.y * 128;
    const int nBase = blockIdx.x * 128;

    // A loader: 128 rows x 8 cols per k-tile. 256 threads x float4.
    const int ar = tid >> 1;            // 0..127
    const int ac = (tid & 1) * 4;       // 0 or 4
    // B loader: 8 rows x 128 cols per k-tile.
    const int br = tid >> 5;            // 0..7
    const int bc = (tid & 31) * 4;      // 0..124

    const int ty = tid >> 4, tx = tid & 15;
    const int row0 = ty * 8, col0 = tx * 8;

    float acc[8][8];
#pragma unroll
    for (int i = 0; i < 8; i++)
#pragma unroll
        for (int j = 0; j < 8; j++) acc[i][j] = 0.f;

    const float* Aptr = A + (size_t)(mBase + ar) * lda + ac;
    const float* Bptr = B + (size_t)br * ldb + nBase + bc;

    for (int k0 = 0; k0 < K; k0 += 8) {
        float4 av = *reinterpret_cast<const float4*>(Aptr + k0);
        float4 bv = *reinterpret_cast<const float4*>(Bptr + (size_t)k0 * ldb);
        __syncthreads();
        As[ac + 0][ar] = av.x; As[ac + 1][ar] = av.y;
        As[ac + 2][ar] = av.z; As[ac + 3][ar] = av.w;
        *reinterpret_cast<float4*>(&Bs[br][bc]) = bv;
        __syncthreads();
#pragma unroll
        for (int kk = 0; kk < 8; kk++) {
            float4 a0 = *reinterpret_cast<const float4*>(&As[kk][row0]);
            float4 a1 = *reinterpret_cast<const float4*>(&As[kk][row0 + 4]);
            float4 b0 = *reinterpret_cast<const float4*>(&Bs[kk][col0]);
            float4 b1 = *reinterpret_cast<const float4*>(&Bs[kk][col0 + 4]);
            float a[8] = {a0.x,a0.y,a0.z,a0.w,a1.x,a1.y,a1.z,a1.w};
            float b[8] = {b0.x,b0.y,b0.z,b0.w,b1.x,b1.y,b1.z,b1.w};
#pragma unroll
            for (int i = 0; i < 8; i++)
#pragma unroll
                for (int j = 0; j < 8; j++) acc[i][j] += a[i] * b[j];
        }
    }

#pragma unroll
    for (int i = 0; i < 8; i++) {
        size_t off = (size_t)(mBase + row0 + i) * ldc + nBase + col0;
#pragma unroll
        for (int j = 0; j < 8; j++) {
            float v = acc[i][j];
            if (Add) v += addScale * Add[off + j];
            C[off + j] = v;
        }
    }
}

// ---------------- sum over H for x and img ----------------
__global__ void sumhw_kernel(const float* __restrict__ x, const float* __restrict__ img,
                             float* __restrict__ xs, float* __restrict__ is_)
{
    int idx = blockIdx.x * 256 + threadIdx.x;
    if (idx >= B_ * WW * HID) return;
    int r = idx >> 10;          // b*28 + w
    int c = idx & 1023;
    int b = r / WW, w = r % WW;
    size_t base = ((size_t)b * (HH * WW) + w) * HID + c;
    float s1 = 0.f, s2 = 0.f;
#pragma unroll 4
    for (int h = 0; h < HH; h++) {
        s1 += x[base];
        s2 += img[base];
        base += (size_t)WW * HID;
    }
    xs[idx] = s1;
    is_[idx] = s2;
}

// ---------------- attention: one block per (b,n,h) ----------------
__global__ void __launch_bounds__(256) attn_kernel(
    const float* __restrict__ Yq, const float* __restrict__ Yk,
    const float* __restrict__ vsum, const float* __restrict__ img,
    float* __restrict__ O)
{
    __shared__ float rq[1792], rk[1792], qs[1792], ks[1792], vs[1792], sc[784];

    const int id = blockIdx.x;
    const int h  = id % HH;
    const int bn = id / HH;
    const int n  = bn & (NH - 1);
    const int b  = bn >> 4;
    const float gamma = 1.f - exp2f(-(float)(5 + n));
    const int tid = threadIdx.x;

    // load raw q/k (alpha add, gamma) and vsum tile
    for (int i = tid; i < 1792; i += 256) {
        int xr = i >> 6, d = i & 63;
        size_t gi = (((size_t)b * (HH * WW) + h * WW + xr) * HID) + n * DH + d;
        float a = ALPHA_F * img[gi];
        rq[i] = Yq[gi] + a;
        rk[i] = (Yk[gi] + a) * gamma;
        vs[i] = vsum[(((size_t)b * WW + xr) * HID) + n * DH + d];
    }
    __syncthreads();

    // axial rope: dims [0,32) rotate by angle h*invf, dims [32,64) by xr*invf
    for (int i = tid; i < 1792; i += 256) {
        int xr = i >> 6, d = i & 63;
        int j = d & 15;
        float ang = (d < 32 ? (float)h : (float)xr) * expf(-(float)j * LN1E4_16);
        float s, c;
        sincosf(ang, &s, &c);
        bool second = (d & 16) != 0;
        int partner = second ? i - 16 : i + 16;
        float sgn = second ? 1.f : -1.f;
        qs[i] = rq[i] * c + sgn * rq[partner] * s;
        ks[i] = rk[i] * c + sgn * rk[partner] * s;
    }
    __syncthreads();

    // scores[x][z] = q[x,:] . k[z,:]
    for (int i = tid; i < 784; i += 256) {
        int xr = i / WW, z = i % WW;
        const float* qp = &qs[xr * DH];
        const float* kp = &ks[z * DH];
        float accv = 0.f;
#pragma unroll 16
        for (int d = 0; d < DH; d++) accv += qp[d] * kp[d];
        sc[i] = accv;
    }
    __syncthreads();

    // out[w][d] = sum_y sc[w][y] * vs[y][d]
    for (int i = tid; i < 1792; i += 256) {
        int w = i >> 6, d = i & 63;
        float accv = 0.f;
#pragma unroll
        for (int y = 0; y < WW; y++) accv += sc[w * WW + y] * vs[y * DH + d];
        O[(size_t)bn * GSZ + h * (WW * DH) + i] = accv;
    }
}

// ---------------- groupnorm stats: one block per (b,n); deterministic ----------------
__global__ void __launch_bounds__(256) stats_kernel(const float* __restrict__ O,
                                                    float* __restrict__ stats)
{
    int bn = blockIdx.x;
    const float* p = O + (size_t)bn * GSZ;
    float s = 0.f, ss = 0.f;
    for (int i = threadIdx.x; i < GSZ; i += 256) {
        float v = p[i];
        s += v;
        ss += v * v;
    }
#pragma unroll
    for (int o = 16; o > 0; o >>= 1) {
        s  += __shfl_down_sync(0xffffffffu, s,  o);
        ss += __shfl_down_sync(0xffffffffu, ss, o);
    }
    __shared__ float sh[16];
    int w = threadIdx.x >> 5, l = threadIdx.x & 31;
    if (l == 0) { sh[w] = s; sh[8 + w] = ss; }
    __syncthreads();
    if (threadIdx.x == 0) {
        float a = 0.f, b2 = 0.f;
#pragma unroll
        for (int i = 0; i < 8; i++) { a += sh[i]; b2 += sh[8 + i]; }
        stats[bn * 2]     = a;
        stats[bn * 2 + 1] = b2;
    }
}

// ---------------- normalize + transpose to (b,H,W,hid) ----------------
__global__ void norm_kernel(const float* __restrict__ O, const float* __restrict__ stats,
                            const float* __restrict__ gnw, const float* __restrict__ gnb,
                            float* __restrict__ Z)
{
    size_t i = (size_t)blockIdx.x * 256 + threadIdx.x;   // exact: 100352*256
    int bn   = (int)(i / GSZ);
    int rem  = (int)(i % GSZ);
    int n = bn & (NH - 1), b = bn >> 4;
    int h = rem / (WW * DH);
    int rem2 = rem % (WW * DH);
    int w = rem2 >> 6, d = rem2 & 63;
    float inv = 1.f / (float)GSZ;
    float mu  = stats[2 * bn] * inv;
    float var = stats[2 * bn + 1] * inv - mu * mu;
    float rstd = rsqrtf(var + 1e-5f);
    float v = (O[i] - mu) * rstd * gnw[n] + gnb[n];
    Z[(((size_t)b * (HH * WW) + h * WW + w) * HID) + n * DH + d] = v;
}

// ---------------- launch ----------------
extern "C" void kernel_launch(void* const* d_in, const int* in_sizes, int n_in,
                              void* d_out, int out_size)
{
    const float* x    = (const float*)d_in[0];
    const float* img  = (const float*)d_in[1];
    const float* qkvw = (const float*)d_in[2];
    const float* ow   = (const float*)d_in[3];
    const float* gnw  = (const float*)d_in[4];
    const float* gnb  = (const float*)d_in[5];
    float* out = (float*)d_out;

    float *Yq, *Yk, *xs, *is_, *vs, *O, *Z, *st;
    cudaGetSymbolAddress((void**)&Yq,  g_Yq);
    cudaGetSymbolAddress((void**)&Yk,  g_Yk);
    cudaGetSymbolAddress((void**)&xs,  g_xsum);
    cudaGetSymbolAddress((void**)&is_, g_isum);
    cudaGetSymbolAddress((void**)&vs,  g_vsum);
    cudaGetSymbolAddress((void**)&O,   g_O);
    cudaGetSymbolAddress((void**)&Z,   g_Z);
    cudaGetSymbolAddress((void**)&st,  g_stats);

    // 1) per-(b,w) sums over H of x and img
    sumhw_kernel<<<(B_ * WW * HID + 255) / 256, 256>>>(x, img, xs, is_);

    // 2) vsum = xsum @ Wv + ALPHA * imgsum   (Wv = qkv_w cols [1024,2048))
    sgemm_kernel<<<dim3(HID / 128, (B_ * WW) / 128), 256>>>(
        xs, qkvw + 1024, vs, is_, ALPHA_F,
        B_ * WW, HID, HID, HID, 3 * HID, HID);

    // 3) Yq = x @ Wq ; Yk = x @ Wk  (cols [0,1024) and [2048,3072))
    sgemm_kernel<<<dim3(HID / 128, ROWS / 128), 256>>>(
        x, qkvw, Yq, nullptr, 0.f, ROWS, HID, HID, HID, 3 * HID, HID);
    sgemm_kernel<<<dim3(HID / 128, ROWS / 128), 256>>>(
        x, qkvw + 2048, Yk, nullptr, 0.f, ROWS, HID, HID, HID, 3 * HID, HID);

    // 4) attention per (b,n,h)
    attn_kernel<<<BNG * HH, 256>>>(Yq, Yk, vs, img, O);

    // 5) deterministic groupnorm stats + normalize/transpose
    stats_kernel<<<BNG, 256>>>(O, st);
    norm_kernel<<<(int)(((size_t)BNG * GSZ) / 256), 256>>>(O, st, gnw, gnb, Z);

    // 6) final projection: out = Z @ o_w
    sgemm_kernel<<<dim3(HID / 128, ROWS / 128), 256>>>(
        Z, ow, out, nullptr, 0.f, ROWS, HID, HID, HID, HID, HID);
}

// round 3
// speedup vs baseline: 2.2351x; 2.2351x over previous
#include <cuda_runtime.h>
#include <cuda_bf16.h>
#include <math.h>
#include <stdint.h>

// ---------------- problem constants ----------------
#define B_    32
#define HH    28
#define WW    28
#define HID   1024
#define NH    16
#define DH    64
#define ROWS  (B_*HH*WW)        // 25088
#define BNG   (B_*NH)           // 512
#define GSZ   (HH*WW*DH)        // 50176

#define ALPHA_F 0.0828476643f
#define LN1E4_16 0.5756462732485114f

// ---------------- scratch ----------------
__device__ float g_Yqk[(size_t)ROWS * 2048];
__device__ float g_isum[B_ * WW * HID];
__device__ float g_vsum[B_ * WW * HID];
__device__ float g_O[(size_t)BNG * GSZ];
__device__ float g_stats[2 * BNG];
__device__ __nv_bfloat16 g_xh[(size_t)ROWS * HID];
__device__ __nv_bfloat16 g_xl[(size_t)ROWS * HID];
__device__ __nv_bfloat16 g_xsh[B_ * WW * HID];
__device__ __nv_bfloat16 g_xsl[B_ * WW * HID];
__device__ __nv_bfloat16 g_Zh[(size_t)ROWS * HID];
__device__ __nv_bfloat16 g_Zl[(size_t)ROWS * HID];
__device__ __nv_bfloat16 g_Wth[3072 * 1024];
__device__ __nv_bfloat16 g_Wtl[3072 * 1024];
__device__ __nv_bfloat16 g_Owh[1024 * 1024];
__device__ __nv_bfloat16 g_Owl[1024 * 1024];

// ---------------- helpers ----------------
__device__ __forceinline__ uint32_t smem_u32(const void* p) {
    uint32_t a;
    asm("{ .reg .u64 t; cvta.to.shared.u64 t, %1; cvt.u32.u64 %0, t; }" : "=r"(a) : "l"(p));
    return a;
}
#define SWZ(x) ((x) ^ (((x) >> 3) & 0x70))

__device__ __forceinline__ void cp16(uint32_t saddr, const void* g) {
    asm volatile("cp.async.cg.shared.global [%0], [%1], 16;" :: "r"(saddr), "l"(g));
}
__device__ __forceinline__ void cp_commit() {
    asm volatile("cp.async.commit_group;" ::: "memory");
}
__device__ __forceinline__ void cp_wait0() {
    asm volatile("cp.async.wait_group 0;" ::: "memory");
}
__device__ __forceinline__ void ldm_x4(uint32_t& r0, uint32_t& r1, uint32_t& r2, uint32_t& r3,
                                       uint32_t addr) {
    asm volatile("ldmatrix.sync.aligned.m8n8.x4.shared.b16 {%0,%1,%2,%3}, [%4];"
                 : "=r"(r0), "=r"(r1), "=r"(r2), "=r"(r3) : "r"(addr));
}
__device__ __forceinline__ void mma16816(float* d, const uint32_t* a, const uint32_t* b) {
    asm volatile(
        "mma.sync.aligned.m16n8k16.row.col.f32.bf16.bf16.f32 "
        "{%0,%1,%2,%3}, {%4,%5,%6,%7}, {%8,%9}, {%0,%1,%2,%3};"
        : "+f"(d[0]), "+f"(d[1]), "+f"(d[2]), "+f"(d[3])
        : "r"(a[0]), "r"(a[1]), "r"(a[2]), "r"(a[3]), "r"(b[0]), "r"(b[1]));
}

// ---------------- fp32 -> bf16 hi/lo split (for x) ----------------
__global__ void split_kernel(const float* __restrict__ X,
                             __nv_bfloat16* __restrict__ Xh,
                             __nv_bfloat16* __restrict__ Xl)
{
    size_t i = ((size_t)blockIdx.x * 256 + threadIdx.x) * 4;   // total 25.7M elems, /4
    float4 v = *(const float4*)(X + i);
    float f[4] = {v.x, v.y, v.z, v.w};
    __nv_bfloat162 h0 = __floats2bfloat162_rn(f[0], f[1]);
    __nv_bfloat162 h1 = __floats2bfloat162_rn(f[2], f[3]);
    __nv_bfloat162 l0 = __floats2bfloat162_rn(f[0] - __bfloat162float(h0.x),
                                              f[1] - __bfloat162float(h0.y));
    __nv_bfloat162 l1 = __floats2bfloat162_rn(f[2] - __bfloat162float(h1.x),
                                              f[3] - __bfloat162float(h1.y));
    *(__nv_bfloat162*)(Xh + i)     = h0;
    *(__nv_bfloat162*)(Xh + i + 2) = h1;
    *(__nv_bfloat162*)(Xl + i)     = l0;
    *(__nv_bfloat162*)(Xl + i + 2) = l1;
}

// ---------------- weight transpose + bf16 split ----------------
__global__ void transcvt_kernel(const float* __restrict__ W, int ldw, int perm,
                                __nv_bfloat16* __restrict__ Th,
                                __nv_bfloat16* __restrict__ Tl)
{
    __shared__ float t[32][33];
    const int nb = blockIdx.x * 32, kb = blockIdx.y * 32;
    const int tx = threadIdx.x & 31, ty = threadIdx.x >> 5;
    int n = nb + tx;
    int sc = perm ? (n < 1024 ? n : (n < 2048 ? n + 1024 : n - 1024)) : n;
#pragma unroll
    for (int i = 0; i < 4; i++)
        t[ty + 8 * i][tx] = W[(size_t)(kb + ty + 8 * i) * ldw + sc];
    __syncthreads();
#pragma unroll
    for (int i = 0; i < 4; i++) {
        int nn = nb + ty + 8 * i, kk = kb + tx;
        float v = t[tx][ty + 8 * i];
        __nv_bfloat16 h = __float2bfloat16_rn(v);
        float r = v - __bfloat162float(h);
        Th[(size_t)nn * 1024 + kk] = h;
        Tl[(size_t)nn * 1024 + kk] = __float2bfloat16_rn(r);
    }
}

// ---------------- HMMA bf16x3 GEMM ----------------
// C[M,N] = A[M,1024] @ Bt[N,1024]^T (+ addScale*Add). Tiles 128x128x64.
#define OFF_AH 0
#define OFF_AL 16384
#define OFF_BH 32768
#define OFF_BL 49152
#define STAGE  65536
#define GSMEM  (2 * STAGE)

__global__ void __launch_bounds__(256, 1) gemm_kernel(
    const __nv_bfloat16* __restrict__ Ah, const __nv_bfloat16* __restrict__ Al,
    const __nv_bfloat16* __restrict__ Bh, const __nv_bfloat16* __restrict__ Bl,
    float* __restrict__ C, const float* __restrict__ Add, float addScale, int ldc)
{
    extern __shared__ char smem[];
    const uint32_t sb = smem_u32(smem);
    const int tid = threadIdx.x, lane = tid & 31, wid = tid >> 5;
    const int warp_m = wid & 3, warp_n = wid >> 2;
    const int mBase = blockIdx.y * 128, nBase = blockIdx.x * 128;

    float acc[2][8][4];
#pragma unroll
    for (int m = 0; m < 2; m++)
#pragma unroll
        for (int n = 0; n < 8; n++)
#pragma unroll
            for (int j = 0; j < 4; j++) acc[m][n][j] = 0.f;

    // loader indices: 4 chunks of 16B per thread per 16KB tile
    const int r0i = tid >> 3, kbi = tid & 7;   // chunk 0: row=tid/8, 16B col=tid%8

    auto load_stage = [&](int c, int s) {
        uint32_t st = sb + s * STAGE;
        size_t kbase = (size_t)c * 64 + kbi * 8;
#pragma unroll
        for (int i = 0; i < 4; i++) {
            int r = r0i + i * 32;
            uint32_t so = SWZ(r * 128 + kbi * 16);
            cp16(st + OFF_AH + so, Ah + (size_t)(mBase + r) * 1024 + kbase);
            cp16(st + OFF_AL + so, Al + (size_t)(mBase + r) * 1024 + kbase);
            cp16(st + OFF_BH + so, Bh + (size_t)(nBase + r) * 1024 + kbase);
            cp16(st + OFF_BL + so, Bl + (size_t)(nBase + r) * 1024 + kbase);
        }
        cp_commit();
    };

    load_stage(0, 0);

    for (int c = 0; c < 16; c++) {
        cp_wait0();
        __syncthreads();
        if (c < 15) load_stage(c + 1, (c + 1) & 1);

        const uint32_t st = sb + (c & 1) * STAGE;
#pragma unroll
        for (int ks = 0; ks < 4; ks++) {
            const int kbyte = ks * 32 + (lane >> 4) * 16;
            uint32_t ah[2][4], al[2][4], bh[8][2], bl[8][2];
#pragma unroll
            for (int mt = 0; mt < 2; mt++) {
                int row = warp_m * 32 + mt * 16 + (lane & 15);
                uint32_t ad = st + OFF_AH + SWZ(row * 128 + kbyte);
                ldm_x4(ah[mt][0], ah[mt][1], ah[mt][2], ah[mt][3], ad);
                ad = st + OFF_AL + SWZ(row * 128 + kbyte);
                ldm_x4(al[mt][0], al[mt][1], al[mt][2], al[mt][3], ad);
            }
#pragma unroll
            for (int np = 0; np < 4; np++) {
                int rown = warp_n * 64 + np * 16 + (lane & 15);
                uint32_t r0, r1, r2, r3;
                uint32_t ad = st + OFF_BH + SWZ(rown * 128 + kbyte);
                ldm_x4(r0, r1, r2, r3, ad);
                bh[2 * np][0] = r0; bh[2 * np][1] = r2;
                bh[2 * np + 1][0] = r1; bh[2 * np + 1][1] = r3;
                ad = st + OFF_BL + SWZ(rown * 128 + kbyte);
                ldm_x4(r0, r1, r2, r3, ad);
                bl[2 * np][0] = r0; bl[2 * np][1] = r2;
                bl[2 * np + 1][0] = r1; bl[2 * np + 1][1] = r3;
            }
#pragma unroll
            for (int mt = 0; mt < 2; mt++)
#pragma unroll
                for (int nt = 0; nt < 8; nt++) {
                    mma16816(acc[mt][nt], ah[mt], bh[nt]);
                    mma16816(acc[mt][nt], ah[mt], bl[nt]);
                    mma16816(acc[mt][nt], al[mt], bh[nt]);
                }
        }
        __syncthreads();
    }

    // epilogue
#pragma unroll
    for (int mt = 0; mt < 2; mt++) {
        int row = mBase + warp_m * 32 + mt * 16 + (lane >> 2);
#pragma unroll
        for (int nt = 0; nt < 8; nt++) {
            int col = nBase + warp_n * 64 + nt * 8 + (lane & 3) * 2;
            size_t o0 = (size_t)row * ldc + col;
            size_t o1 = (size_t)(row + 8) * ldc + col;
            if (Add) {
                C[o0]     = acc[mt][nt][0] + addScale * Add[o0];
                C[o0 + 1] = acc[mt][nt][1] + addScale * Add[o0 + 1];
                C[o1]     = acc[mt][nt][2] + addScale * Add[o1];
                C[o1 + 1] = acc[mt][nt][3] + addScale * Add[o1 + 1];
            } else {
                *(float2*)(C + o0) = make_float2(acc[mt][nt][0], acc[mt][nt][1]);
                *(float2*)(C + o1) = make_float2(acc[mt][nt][2], acc[mt][nt][3]);
            }
        }
    }
}

// ---------------- sum over H of x and img (emits split bf16 for xsum) ----------------
__global__ void sumhw_kernel(const float* __restrict__ x, const float* __restrict__ img,
                             __nv_bfloat16* __restrict__ xsh, __nv_bfloat16* __restrict__ xsl,
                             float* __restrict__ is_)
{
    int idx = blockIdx.x * 256 + threadIdx.x;
    if (idx >= B_ * WW * HID) return;
    int r = idx >> 10;
    int b = r / WW, w = r % WW;
    size_t base = ((size_t)b * (HH * WW) + w) * HID + (idx & 1023);
    float s1 = 0.f, s2 = 0.f;
#pragma unroll 4
    for (int h = 0; h < HH; h++) {
        s1 += x[base];
        s2 += img[base];
        base += (size_t)WW * HID;
    }
    __nv_bfloat16 hh = __float2bfloat16_rn(s1);
    xsh[idx] = hh;
    xsl[idx] = __float2bfloat16_rn(s1 - __bfloat162float(hh));
    is_[idx] = s2;
}

// ---------------- attention per (b,n,h) ----------------
__global__ void __launch_bounds__(256) attn_kernel(
    const float* __restrict__ Yqk, const float* __restrict__ vsum,
    const float* __restrict__ img, float* __restrict__ O)
{
    __shared__ float rq[1792], rk[1792], qs[1792], ks[1792], vs[1792], sc[784];

    const int id = blockIdx.x;
    const int h  = id % HH;
    const int bn = id / HH;
    const int n  = bn & (NH - 1);
    const int b  = bn >> 4;
    const float gamma = 1.f - exp2f(-(float)(5 + n));
    const int tid = threadIdx.x;

    for (int i = tid; i < 1792; i += 256) {
        int xr = i >> 6, d = i & 63;
        size_t rowbase = ((size_t)b * (HH * WW) + h * WW + xr);
        size_t gq = rowbase * 2048 + n * DH + d;
        size_t gi = rowbase * 1024 + n * DH + d;
        float a = ALPHA_F * img[gi];
        rq[i] = Yqk[gq] + a;
        rk[i] = (Yqk[gq + 1024] + a) * gamma;
        vs[i] = vsum[(((size_t)b * WW + xr) * HID) + n * DH + d];
    }
    __syncthreads();

    for (int i = tid; i < 1792; i += 256) {
        int xr = i >> 6, d = i & 63;
        int j = d & 15;
        float ang = (d < 32 ? (float)h : (float)xr) * expf(-(float)j * LN1E4_16);
        float s, c;
        sincosf(ang, &s, &c);
        bool second = (d & 16) != 0;
        int partner = second ? i - 16 : i + 16;
        float sgn = second ? 1.f : -1.f;
        qs[i] = rq[i] * c + sgn * rq[partner] * s;
        ks[i] = rk[i] * c + sgn * rk[partner] * s;
    }
    __syncthreads();

    for (int i = tid; i < 784; i += 256) {
        int xr = i / WW, z = i % WW;
        const float* qp = &qs[xr * DH];
        const float* kp = &ks[z * DH];
        float accv = 0.f;
#pragma unroll 16
        for (int d = 0; d < DH; d++) accv += qp[d] * kp[d];
        sc[i] = accv;
    }
    __syncthreads();

    for (int i = tid; i < 1792; i += 256) {
        int w = i >> 6, d = i & 63;
        float accv = 0.f;
#pragma unroll
        for (int y = 0; y < WW; y++) accv += sc[w * WW + y] * vs[y * DH + d];
        O[(size_t)bn * GSZ + h * (WW * DH) + i] = accv;
    }
}

// ---------------- groupnorm stats ----------------
__global__ void __launch_bounds__(256) stats_kernel(const float* __restrict__ O,
                                                    float* __restrict__ stats)
{
    int bn = blockIdx.x;
    const float* p = O + (size_t)bn * GSZ;
    float s = 0.f, ss = 0.f;
    for (int i = threadIdx.x; i < GSZ; i += 256) {
        float v = p[i];
        s += v; ss += v * v;
    }
#pragma unroll
    for (int o = 16; o > 0; o >>= 1) {
        s  += __shfl_down_sync(0xffffffffu, s,  o);
        ss += __shfl_down_sync(0xffffffffu, ss, o);
    }
    __shared__ float sh[16];
    int w = threadIdx.x >> 5, l = threadIdx.x & 31;
    if (l == 0) { sh[w] = s; sh[8 + w] = ss; }
    __syncthreads();
    if (threadIdx.x == 0) {
        float a = 0.f, b2 = 0.f;
#pragma unroll
        for (int i = 0; i < 8; i++) { a += sh[i]; b2 += sh[8 + i]; }
        stats[bn * 2] = a;
        stats[bn * 2 + 1] = b2;
    }
}

// ---------------- normalize + transpose -> split bf16 Z ----------------
__global__ void norm_kernel(const float* __restrict__ O, const float* __restrict__ stats,
                            const float* __restrict__ gnw, const float* __restrict__ gnb,
                            __nv_bfloat16* __restrict__ Zh, __nv_bfloat16* __restrict__ Zl)
{
    size_t i = (size_t)blockIdx.x * 256 + threadIdx.x;
    int bn = (int)(i / GSZ);
    int rem = (int)(i % GSZ);
    int n = bn & (NH - 1), b = bn >> 4;
    int h = rem / (WW * DH);
    int rem2 = rem % (WW * DH);
    int w = rem2 >> 6, d = rem2 & 63;
    float inv = 1.f / (float)GSZ;
    float mu  = stats[2 * bn] * inv;
    float var = stats[2 * bn + 1] * inv - mu * mu;
    float rstd = rsqrtf(var + 1e-5f);
    float v = (O[i] - mu) * rstd * gnw[n] + gnb[n];
    size_t zo = (((size_t)b * (HH * WW) + h * WW + w) * HID) + n * DH + d;
    __nv_bfloat16 hh = __float2bfloat16_rn(v);
    Zh[zo] = hh;
    Zl[zo] = __float2bfloat16_rn(v - __bfloat162float(hh));
}

// ---------------- launch ----------------
extern "C" void kernel_launch(void* const* d_in, const int* in_sizes, int n_in,
                              void* d_out, int out_size)
{
    const float* x    = (const float*)d_in[0];
    const float* img  = (const float*)d_in[1];
    const float* qkvw = (const float*)d_in[2];
    const float* ow   = (const float*)d_in[3];
    const float* gnw  = (const float*)d_in[4];
    const float* gnb  = (const float*)d_in[5];
    float* out = (float*)d_out;

    float *Yqk, *is_, *vs, *O, *st;
    __nv_bfloat16 *xh, *xl, *xsh, *xsl, *Zh, *Zl, *Wth, *Wtl, *Owh, *Owl;
    cudaGetSymbolAddress((void**)&Yqk, g_Yqk);
    cudaGetSymbolAddress((void**)&is_, g_isum);
    cudaGetSymbolAddress((void**)&vs,  g_vsum);
    cudaGetSymbolAddress((void**)&O,   g_O);
    cudaGetSymbolAddress((void**)&st,  g_stats);
    cudaGetSymbolAddress((void**)&xh,  g_xh);
    cudaGetSymbolAddress((void**)&xl,  g_xl);
    cudaGetSymbolAddress((void**)&xsh, g_xsh);
    cudaGetSymbolAddress((void**)&xsl, g_xsl);
    cudaGetSymbolAddress((void**)&Zh,  g_Zh);
    cudaGetSymbolAddress((void**)&Zl,  g_Zl);
    cudaGetSymbolAddress((void**)&Wth, g_Wth);
    cudaGetSymbolAddress((void**)&Wtl, g_Wtl);
    cudaGetSymbolAddress((void**)&Owh, g_Owh);
    cudaGetSymbolAddress((void**)&Owl, g_Owl);

    cudaFuncSetAttribute(gemm_kernel, cudaFuncAttributeMaxDynamicSharedMemorySize, GSMEM);

    // 0) weight transpose + split; x split; sums
    transcvt_kernel<<<dim3(96, 32), 256>>>(qkvw, 3072, 1, Wth, Wtl);
    transcvt_kernel<<<dim3(32, 32), 256>>>(ow,   1024, 0, Owh, Owl);
    split_kernel<<<(ROWS * HID) / 1024, 256>>>(x, xh, xl);
    sumhw_kernel<<<(B_ * WW * HID + 255) / 256, 256>>>(x, img, xsh, xsl, is_);

    // 1) vsum = xsum @ Wv + ALPHA*isum  (M=896, N=1024; Wv = rows [2048,3072))
    gemm_kernel<<<dim3(8, 7), 256, GSMEM>>>(
        xsh, xsl, Wth + (size_t)2048 * 1024, Wtl + (size_t)2048 * 1024,
        vs, is_, ALPHA_F, 1024);

    // 2) Yqk = x @ [Wq | Wk]  (M=25088, N=2048)
    gemm_kernel<<<dim3(16, 196), 256, GSMEM>>>(
        xh, xl, Wth, Wtl, Yqk, nullptr, 0.f, 2048);

    // 3) attention
    attn_kernel<<<BNG * HH, 256>>>(Yqk, vs, img, O);

    // 4) groupnorm -> split Z
    stats_kernel<<<BNG, 256>>>(O, st);
    norm_kernel<<<(int)(((size_t)BNG * GSZ) / 256), 256>>>(O, st, gnw, gnb, Zh, Zl);

    // 5) out = Z @ o_w  (M=25088, N=1024)
    gemm_kernel<<<dim3(8, 196), 256, GSMEM>>>(
        Zh, Zl, Owh, Owl, out, nullptr, 0.f, 1024);
}